// round 7
// baseline (speedup 1.0000x reference)
#include <cuda_runtime.h>
#include <math_constants.h>

#define B_CONST 4096
#define D_CONST 256
#define N_CONST 8192
#define GRID    128
#define TPB     1024

// scratch (device globals — allocation is forbidden)
__device__ int g_idxmax[N_CONST];
__device__ int g_barrier = 0;   // 0 -> 128 (release) -> 256 (reset to 0)

__device__ __forceinline__ float pick4(float4 v, int s) {
    float r = v.x;
    if (s == 1) r = v.y;
    if (s == 2) r = v.z;
    if (s == 3) r = v.w;
    return r;
}

__global__ void __launch_bounds__(TPB, 1)
fused_kernel(const float* __restrict__ a,
             const float* __restrict__ b,
             const int*   __restrict__ negc,
             float* __restrict__ out,   // [0]=loss, [1..256]=num_max
             int out_n) {
    const int tid  = threadIdx.x;
    const int bid  = blockIdx.x;
    const int warp = tid >> 5;
    const int lane = tid & 31;
    const unsigned F = 0xffffffffu;

    __shared__ float s_max[64];   // [0..31]=a-rows, [32..63]=b-rows
    __shared__ int   s_idx[64];
    __shared__ float s_pos[32];   // per-warp positive pair sums

    // zero output (poisoned 0xAA); ordered before phase-2 atomics by barrier
    if (bid == 0 && tid < out_n) out[tid] = 0.0f;

    // ---- Phase 1: warp handles PAIR (a-row arow  <->  b-row arow) ----
    const int arow = bid * 32 + warp;              // 0..4095
    const float* r0 = a + (size_t)arow * D_CONST;
    const float* r1 = b + (size_t)arow * D_CONST;
    const int c0 = lane * 4;
    const int c1 = 128 + lane * 4;

    float4 v00 = *reinterpret_cast<const float4*>(r0 + c0);
    float4 v01 = *reinterpret_cast<const float4*>(r0 + c1);
    float4 v10 = *reinterpret_cast<const float4*>(r1 + c0);
    float4 v11 = *reinterpret_cast<const float4*>(r1 + c1);

    // per-lane best, increasing column order -> first-occurrence tie-break
    float best0 = v00.x; int bi0 = c0;
    if (v00.y > best0) { best0 = v00.y; bi0 = c0 + 1; }
    if (v00.z > best0) { best0 = v00.z; bi0 = c0 + 2; }
    if (v00.w > best0) { best0 = v00.w; bi0 = c0 + 3; }
    if (v01.x > best0) { best0 = v01.x; bi0 = c1;     }
    if (v01.y > best0) { best0 = v01.y; bi0 = c1 + 1; }
    if (v01.z > best0) { best0 = v01.z; bi0 = c1 + 2; }
    if (v01.w > best0) { best0 = v01.w; bi0 = c1 + 3; }

    float best1 = v10.x; int bi1 = c0;
    if (v10.y > best1) { best1 = v10.y; bi1 = c0 + 1; }
    if (v10.z > best1) { best1 = v10.z; bi1 = c0 + 2; }
    if (v10.w > best1) { best1 = v10.w; bi1 = c0 + 3; }
    if (v11.x > best1) { best1 = v11.x; bi1 = c1;     }
    if (v11.y > best1) { best1 = v11.y; bi1 = c1 + 1; }
    if (v11.z > best1) { best1 = v11.z; bi1 = c1 + 2; }
    if (v11.w > best1) { best1 = v11.w; bi1 = c1 + 3; }

    // warp reduce: max value, min index on ties (matches jnp.argmax)
    #pragma unroll
    for (int off = 16; off; off >>= 1) {
        float ov0 = __shfl_down_sync(F, best0, off);
        int   oi0 = __shfl_down_sync(F, bi0,   off);
        float ov1 = __shfl_down_sync(F, best1, off);
        int   oi1 = __shfl_down_sync(F, bi1,   off);
        if (ov0 > best0 || (ov0 == best0 && oi0 < bi0)) { best0 = ov0; bi0 = oi0; }
        if (ov1 > best1 || (ov1 == best1 && oi1 < bi1)) { best1 = ov1; bi1 = oi1; }
    }
    const float m0 = __shfl_sync(F, best0, 0);
    const int   j0 = __shfl_sync(F, bi0,   0);
    const float m1 = __shfl_sync(F, best1, 0);
    const int   j1 = __shfl_sync(F, bi1,   0);

    // positives in-register: pos_a = m0 - row_a[j1] ; pos_b = m1 - row_b[j0]
    float xa = pick4(v00, j1 & 3), ya = pick4(v01, j1 & 3);
    float fa = __shfl_sync(F, (j1 < 128) ? xa : ya, (j1 >> 2) & 31);
    float xb = pick4(v10, j0 & 3), yb = pick4(v11, j0 & 3);
    float fb = __shfl_sync(F, (j0 < 128) ? xb : yb, (j0 >> 2) & 31);

    if (lane == 0) {
        g_idxmax[arow]           = j0;   // global: needed by random negatives
        g_idxmax[arow + B_CONST] = j1;
        s_max[warp]      = m0;  s_idx[warp]      = j0;
        s_max[warp + 32] = m1;  s_idx[warp + 32] = j1;
        s_pos[warp] = (m0 - fa) + (m1 - fb);
    }

    // ---- pre-barrier: neg column + row ptr for this block's 64 rows ----
    int ccol = 0;
    const float* rowp = nullptr;
    if (tid < 64) {
        const int grow = (tid < 32) ? (bid * 32 + tid)
                                    : (B_CONST + bid * 32 + (tid - 32));
        const int pair = grow ^ B_CONST;
        const int e1 = min(grow, pair);
        const int e2 = max(grow, pair);
        int c = negc[grow];
        c += (c >= e1) ? 1 : 0;
        c += (c >= e2) ? 1 : 0;
        ccol = c;
        rowp = (tid < 32) ? (a + (size_t)(bid * 32 + tid) * D_CONST)
                          : (b + (size_t)(bid * 32 + (tid - 32)) * D_CONST);
    }

    // ---- grid barrier: 1 atomic arrive, plain-load busy spin ----
    __threadfence();                 // release: publish g_idxmax (+ zeroed out)
    __syncthreads();
    if (tid == 0) {
        atomicAdd(&g_barrier, 1);
        volatile int* bar = &g_barrier;
        while (*bar < GRID) { }      // tight poll: fastest wake-up
    }
    __syncthreads();
    __threadfence();                 // acquire

    // ---- Phase 2: negatives (2-level chain) + hist + loss ----
    if (tid < 64) {
        atomicAdd(&out[1 + s_idx[tid]], 1.0f);       // hist (fire-and-forget)

        const int j2   = g_idxmax[ccol];             // L2 (only global dep)
        const float nf = s_max[tid] - rowp[j2];      // L1-hot gather
        const float m  = fmaxf(1.0f - nf, 0.0f);
        float contrib  = m * m;

        // fold block's positive partial into warp0-lane0's contribution
        if (tid < 32) {
            float p = s_pos[lane];
            #pragma unroll
            for (int off = 16; off; off >>= 1)
                p += __shfl_down_sync(F, p, off);
            if (lane == 0) contrib += p;
        }
        #pragma unroll
        for (int off = 16; off; off >>= 1)
            contrib += __shfl_down_sync(F, contrib, off);
        if (lane == 0)
            atomicAdd(&out[0], 0.5f * contrib);      // 2 atomics per block
    }

    // ---- barrier reset, off the critical path (replay-safe) ----
    if (tid == 0) {
        const int old = atomicAdd(&g_barrier, 1);
        if (old == 2 * GRID - 1) atomicExch(&g_barrier, 0);
    }
}

extern "C" void kernel_launch(void* const* d_in, const int* in_sizes, int n_in,
                              void* d_out, int out_size) {
    const float* a    = (const float*)d_in[0];   // out_a [4096,256] f32
    const float* b    = (const float*)d_in[1];   // out_b [4096,256] f32
    const int*   negc = (const int*)  d_in[2];   // neg_choice [8192] i32
    float* out = (float*)d_out;

    fused_kernel<<<GRID, TPB>>>(a, b, negc, out, out_size);
}

// round 8
// speedup vs baseline: 1.0029x; 1.0029x over previous
#include <cuda_runtime.h>
#include <math_constants.h>

#define B_CONST 4096
#define D_CONST 256
#define N_CONST 8192
#define GRID    128
#define TPB     1024

// scratch (device globals — allocation is forbidden; zero-initialized at load)
// slot packing: (epoch << 8) | idxmax   (idxmax < 256). Epochs advance in
// lockstep: every slot written exactly once per launch.
__device__ int g_slot[N_CONST];
__device__ int g_zflag = 0;     // epoch of "output zeroed" by block 0

__device__ __forceinline__ float pick4(float4 v, int s) {
    float r = v.x;
    if (s == 1) r = v.y;
    if (s == 2) r = v.z;
    if (s == 3) r = v.w;
    return r;
}

__global__ void __launch_bounds__(TPB, 1)
fused_kernel(const float* __restrict__ a,
             const float* __restrict__ b,
             const int*   __restrict__ negc,
             float* __restrict__ out,   // [0]=loss, [1..256]=num_max
             int out_n) {
    const int tid  = threadIdx.x;
    const int bid  = blockIdx.x;
    const int warp = tid >> 5;
    const int lane = tid & 31;
    const unsigned F = 0xffffffffu;

    __shared__ float s_max[64];
    __shared__ int   s_idx[64];
    __shared__ float s_pos[32];
    __shared__ int   s_epoch;

    // ---- entry: derive this launch's epoch from own slot (overlaps loads) ----
    if (tid == 0) {
        const int old = *(volatile int*)&g_slot[bid * 32];
        s_epoch = (old >> 8) + 1;
    }

    // zero output (poisoned 0xAA); other blocks gate on g_zflag before atomics
    if (bid == 0 && tid < out_n) out[tid] = 0.0f;

    // ---- Phase 1: warp handles PAIR (a-row arow  <->  b-row arow) ----
    const int arow = bid * 32 + warp;              // 0..4095
    const float* r0 = a + (size_t)arow * D_CONST;
    const float* r1 = b + (size_t)arow * D_CONST;
    const int c0 = lane * 4;
    const int c1 = 128 + lane * 4;

    float4 v00 = *reinterpret_cast<const float4*>(r0 + c0);
    float4 v01 = *reinterpret_cast<const float4*>(r0 + c1);
    float4 v10 = *reinterpret_cast<const float4*>(r1 + c0);
    float4 v11 = *reinterpret_cast<const float4*>(r1 + c1);

    // per-lane best, increasing column order -> first-occurrence tie-break
    float best0 = v00.x; int bi0 = c0;
    if (v00.y > best0) { best0 = v00.y; bi0 = c0 + 1; }
    if (v00.z > best0) { best0 = v00.z; bi0 = c0 + 2; }
    if (v00.w > best0) { best0 = v00.w; bi0 = c0 + 3; }
    if (v01.x > best0) { best0 = v01.x; bi0 = c1;     }
    if (v01.y > best0) { best0 = v01.y; bi0 = c1 + 1; }
    if (v01.z > best0) { best0 = v01.z; bi0 = c1 + 2; }
    if (v01.w > best0) { best0 = v01.w; bi0 = c1 + 3; }

    float best1 = v10.x; int bi1 = c0;
    if (v10.y > best1) { best1 = v10.y; bi1 = c0 + 1; }
    if (v10.z > best1) { best1 = v10.z; bi1 = c0 + 2; }
    if (v10.w > best1) { best1 = v10.w; bi1 = c0 + 3; }
    if (v11.x > best1) { best1 = v11.x; bi1 = c1;     }
    if (v11.y > best1) { best1 = v11.y; bi1 = c1 + 1; }
    if (v11.z > best1) { best1 = v11.z; bi1 = c1 + 2; }
    if (v11.w > best1) { best1 = v11.w; bi1 = c1 + 3; }

    // warp reduce: max value, min index on ties (matches jnp.argmax)
    #pragma unroll
    for (int off = 16; off; off >>= 1) {
        float ov0 = __shfl_down_sync(F, best0, off);
        int   oi0 = __shfl_down_sync(F, bi0,   off);
        float ov1 = __shfl_down_sync(F, best1, off);
        int   oi1 = __shfl_down_sync(F, bi1,   off);
        if (ov0 > best0 || (ov0 == best0 && oi0 < bi0)) { best0 = ov0; bi0 = oi0; }
        if (ov1 > best1 || (ov1 == best1 && oi1 < bi1)) { best1 = ov1; bi1 = oi1; }
    }
    const float m0 = __shfl_sync(F, best0, 0);
    const int   j0 = __shfl_sync(F, bi0,   0);
    const float m1 = __shfl_sync(F, best1, 0);
    const int   j1 = __shfl_sync(F, bi1,   0);

    // positives in-register: pos_a = m0 - row_a[j1] ; pos_b = m1 - row_b[j0]
    float xa = pick4(v00, j1 & 3), ya = pick4(v01, j1 & 3);
    float fa = __shfl_sync(F, (j1 < 128) ? xa : ya, (j1 >> 2) & 31);
    float xb = pick4(v10, j0 & 3), yb = pick4(v11, j0 & 3);
    float fb = __shfl_sync(F, (j0 < 128) ? xb : yb, (j0 >> 2) & 31);

    // ---- pre-publish: neg column + row ptr for this block's 64 rows ----
    int ccol = 0;
    const float* rowp = nullptr;
    if (tid < 64) {
        const int grow = (tid < 32) ? (bid * 32 + tid)
                                    : (B_CONST + bid * 32 + (tid - 32));
        const int pair = grow ^ B_CONST;
        const int e1 = min(grow, pair);
        const int e2 = max(grow, pair);
        int c = negc[grow];
        c += (c >= e1) ? 1 : 0;
        c += (c >= e2) ? 1 : 0;
        ccol = c;
        rowp = (tid < 32) ? (a + (size_t)(bid * 32 + tid) * D_CONST)
                          : (b + (size_t)(bid * 32 + (tid - 32)) * D_CONST);
    }

    __syncthreads();                      // s_epoch visible to all
    const int epoch = s_epoch;

    // publish slots (the packed word is its own ready flag — no fences)
    if (lane == 0) {
        *(volatile int*)&g_slot[arow]           = (epoch << 8) | j0;
        *(volatile int*)&g_slot[arow + B_CONST] = (epoch << 8) | j1;
        s_max[warp]      = m0;  s_idx[warp]      = j0;
        s_max[warp + 32] = m1;  s_idx[warp + 32] = j1;
        s_pos[warp] = (m0 - fa) + (m1 - fb);
    }
    // block 0: signal "output zeroed" (zero stores ordered by bar + fence)
    if (bid == 0 && tid == 0) {
        __threadfence();
        *(volatile int*)&g_zflag = epoch;
    }

    __syncthreads();                      // s_max/s_idx/s_pos visible

    // ---- Phase 2: per-value spins, no grid rendezvous ----
    if (tid < 64) {
        // gate on output being zeroed (block 0 signals ~start of kernel)
        volatile int* zf = &g_zflag;
        while (*zf != epoch) { }

        atomicAdd(&out[1 + s_idx[tid]], 1.0f);       // hist (fire-and-forget)

        // spin directly on the needed slot: wait only for OUR producer
        volatile int* sp = &g_slot[ccol];
        int v = *sp;
        while ((v >> 8) != epoch) v = *sp;
        const int j2 = v & 255;

        const float nf = s_max[tid] - rowp[j2];      // L1-hot gather
        const float m  = fmaxf(1.0f - nf, 0.0f);
        float contrib  = m * m;

        if (tid < 32) {                              // fold positive partials
            float p = s_pos[lane];
            #pragma unroll
            for (int off = 16; off; off >>= 1)
                p += __shfl_down_sync(F, p, off);
            if (lane == 0) contrib += p;
        }
        #pragma unroll
        for (int off = 16; off; off >>= 1)
            contrib += __shfl_down_sync(F, contrib, off);
        if (lane == 0)
            atomicAdd(&out[0], 0.5f * contrib);      // 2 atomics per block
    }
}

extern "C" void kernel_launch(void* const* d_in, const int* in_sizes, int n_in,
                              void* d_out, int out_size) {
    const float* a    = (const float*)d_in[0];   // out_a [4096,256] f32
    const float* b    = (const float*)d_in[1];   // out_b [4096,256] f32
    const int*   negc = (const int*)  d_in[2];   // neg_choice [8192] i32
    float* out = (float*)d_out;

    fused_kernel<<<GRID, TPB>>>(a, b, negc, out, out_size);
}